// round 2
// baseline (speedup 1.0000x reference)
#include <cuda_runtime.h>
#include <cstdint>

// Problem constants (fixed shapes)
#define B_    16
#define T_    2048
#define P_    64      // channels == number of nets
#define LAG_  5
#define H0_   32
#define H1_   32
#define TOUT_ (T_ - LAG_ + 1)   // 2044

#define TILE_  256
#define NT_    128
#define XROW_  262              // smem row stride for Xs (even -> float2 aligned)

// Pre-transposed weight scratch (allowed: __device__ globals, no allocation)
__device__ float g_W0t[P_ * (P_ * LAG_) * H0_];  // [n][c*LAG+l][h]  (h contiguous)
__device__ float g_W1t[P_ * H0_ * H1_];          // [n][i][o]        (o contiguous)

typedef unsigned long long ull;

__device__ __forceinline__ ull pk(float lo, float hi) {
    ull r;
    asm("mov.b64 %0, {%1, %2};" : "=l"(r) : "f"(lo), "f"(hi));
    return r;
}
__device__ __forceinline__ void upk(ull v, float& lo, float& hi) {
    asm("mov.b64 {%0, %1}, %2;" : "=f"(lo), "=f"(hi) : "l"(v));
}
__device__ __forceinline__ ull fma2(ull a, ull b, ull c) {
    ull d;
    asm("fma.rn.f32x2 %0, %1, %2, %3;" : "=l"(d) : "l"(a), "l"(b), "l"(c));
    return d;
}

// ---------------------------------------------------------------------------
// Prologue: transpose W0 -> [n][c*LAG+l][h], W1 -> [n][i][o]
// ---------------------------------------------------------------------------
__global__ void prep_weights(const float* __restrict__ W0,
                             const float* __restrict__ W1) {
    const int stride = gridDim.x * blockDim.x;
    const int tid0 = blockIdx.x * blockDim.x + threadIdx.x;

    const int TOT0 = P_ * (P_ * LAG_) * H0_;  // 64*320*32
    for (int d = tid0; d < TOT0; d += stride) {
        int n  = d / ((P_ * LAG_) * H0_);
        int r  = d - n * ((P_ * LAG_) * H0_);
        int cl = r >> 5;
        int h  = r & 31;
        int c  = cl / LAG_;
        int l  = cl - c * LAG_;
        g_W0t[d] = W0[(((n * H0_ + h) * P_ + c) * LAG_) + l];
    }
    const int TOT1 = P_ * H0_ * H1_;  // 64*32*32
    for (int d = tid0; d < TOT1; d += stride) {
        int n = d >> 10;
        int r = d & 1023;
        int i = r >> 5;
        int o = r & 31;
        g_W1t[d] = W1[((n * H1_ + o) * H0_) + i];
    }
}

// ---------------------------------------------------------------------------
// Head (layer1 + layer2) for one timestep, from layer0 accumulators
// ---------------------------------------------------------------------------
__device__ __forceinline__ float mlp_head(const ull (&acc)[16],
                                          const float* __restrict__ W1s,
                                          const float* __restrict__ bss) {
    // ReLU(layer0)
    float a[H0_];
#pragma unroll
    for (int q = 0; q < 16; ++q) {
        float lo, hi;
        upk(acc[q], lo, hi);
        a[2 * q]     = fmaxf(lo, 0.0f);
        a[2 * q + 1] = fmaxf(hi, 0.0f);
    }
    // layer1: c2[o] = b1[o] + sum_i a[i] * W1[n][o][i]   (W1s is [i][o])
    ull c2[16];
#pragma unroll
    for (int q = 0; q < 16; ++q)
        c2[q] = pk(bss[32 + 2 * q], bss[32 + 2 * q + 1]);
#pragma unroll 8
    for (int i = 0; i < H0_; ++i) {
        ull xa = pk(a[i], a[i]);
        const ulonglong2* wp1 = (const ulonglong2*)(W1s + i * H1_);
#pragma unroll
        for (int q = 0; q < 8; ++q) {
            ulonglong2 w = wp1[q];
            c2[2 * q]     = fma2(xa, w.x, c2[2 * q]);
            c2[2 * q + 1] = fma2(xa, w.y, c2[2 * q + 1]);
        }
    }
    // layer2: r = b2 + sum_o relu(c2[o]) * W2[n][o]
    float r = bss[96];
#pragma unroll
    for (int q = 0; q < 16; ++q) {
        float lo, hi;
        upk(c2[q], lo, hi);
        r = fmaf(fmaxf(lo, 0.0f), bss[64 + 2 * q], r);
        r = fmaf(fmaxf(hi, 0.0f), bss[64 + 2 * q + 1], r);
    }
    return r;
}

// ---------------------------------------------------------------------------
// Main kernel: one block per (t-tile, net, batch). 128 threads, 2 t each.
// ---------------------------------------------------------------------------
__global__ __launch_bounds__(NT_, 2)
void cmlp_kernel(const float* __restrict__ X,
                 const float* __restrict__ b0,
                 const float* __restrict__ b1,
                 const float* __restrict__ W2,
                 const float* __restrict__ b2,
                 float* __restrict__ out) {
    extern __shared__ float smem[];
    float* W0s = smem;                       // 10240 floats: [c*LAG+l][h]
    float* W1s = smem + 10240;               // 1024 floats:  [i][o]
    float* Xs  = smem + 11264;               // 64 * XROW_ floats: [c][t_local]
    float* bss = smem + 11264 + P_ * XROW_;  // b0[32] | b1[32] | W2[32] | b2

    const int t0  = blockIdx.x * TILE_;
    const int n   = blockIdx.y;
    const int bb  = blockIdx.z;
    const int tid = threadIdx.x;

    // --- load pre-transposed weights (coalesced float4) ---
    {
        const float4* s0 = (const float4*)(g_W0t + n * (P_ * LAG_ * H0_));
        float4* d0 = (float4*)W0s;
#pragma unroll 4
        for (int i = tid; i < (P_ * LAG_ * H0_) / 4; i += NT_) d0[i] = s0[i];
        const float4* s1 = (const float4*)(g_W1t + n * (H0_ * H1_));
        float4* d1 = (float4*)W1s;
#pragma unroll 2
        for (int i = tid; i < (H0_ * H1_) / 4; i += NT_) d1[i] = s1[i];
        if (tid < 32) {
            bss[tid]      = b0[n * H0_ + tid];
            bss[32 + tid] = b1[n * H1_ + tid];
            bss[64 + tid] = W2[n * H1_ + tid];
        }
        if (tid == 0) bss[96] = b2[n];
    }

    // --- stage X tile transposed: Xs[c][i] = X[bb][t0+i][c], i in [0, 260) ---
    {
        const int NI = TILE_ + LAG_ - 1;  // 260
        for (int m = tid; m < NI * (P_ / 4); m += NT_) {
            int i  = m >> 4;          // 0..259
            int c4 = m & 15;          // 0..15
            int t  = t0 + i;
            float4 v = make_float4(0.f, 0.f, 0.f, 0.f);
            if (t < T_) v = *(const float4*)(X + ((size_t)bb * T_ + t) * P_ + 4 * c4);
            Xs[(4 * c4 + 0) * XROW_ + i] = v.x;
            Xs[(4 * c4 + 1) * XROW_ + i] = v.y;
            Xs[(4 * c4 + 2) * XROW_ + i] = v.z;
            Xs[(4 * c4 + 3) * XROW_ + i] = v.w;
        }
    }
    __syncthreads();

    const int tt    = 2 * tid;       // local time
    const int tglob = t0 + tt;
    if (tglob >= TOUT_) return;      // whole-thread early exit (after barrier)

    // --- layer0: acc[t][h] = b0[h] + sum_{c,l} X[t+l][c] * W0[h][c][l] ---
    ull acc0[16], acc1[16];
#pragma unroll
    for (int q = 0; q < 16; ++q) {
        ull bv = pk(bss[2 * q], bss[2 * q + 1]);
        acc0[q] = bv;
        acc1[q] = bv;
    }

#pragma unroll 2
    for (int c = 0; c < P_; ++c) {
        const float* xr = Xs + c * XROW_ + tt;
        float2 x01 = *(const float2*)(xr);
        float2 x23 = *(const float2*)(xr + 2);
        float2 x45 = *(const float2*)(xr + 4);
        float xv[6] = {x01.x, x01.y, x23.x, x23.y, x45.x, x45.y};
        const ulonglong2* wp = (const ulonglong2*)(W0s + c * (LAG_ * H0_));
#pragma unroll
        for (int l = 0; l < LAG_; ++l) {
            ull xa = pk(xv[l], xv[l]);
            ull xb = pk(xv[l + 1], xv[l + 1]);
#pragma unroll
            for (int q = 0; q < 8; ++q) {
                ulonglong2 w = wp[l * 8 + q];
                acc0[2 * q]     = fma2(xa, w.x, acc0[2 * q]);
                acc0[2 * q + 1] = fma2(xa, w.y, acc0[2 * q + 1]);
                acc1[2 * q]     = fma2(xb, w.x, acc1[2 * q]);
                acc1[2 * q + 1] = fma2(xb, w.y, acc1[2 * q + 1]);
            }
        }
    }

    // --- layers 1+2 per timestep, then store ---
    float r0 = mlp_head(acc0, W1s, bss);
    out[((size_t)bb * TOUT_ + tglob) * P_ + n] = r0;
    if (tglob + 1 < TOUT_) {
        float r1 = mlp_head(acc1, W1s, bss);
        out[((size_t)bb * TOUT_ + tglob + 1) * P_ + n] = r1;
    }
}

// ---------------------------------------------------------------------------
// Launch
// ---------------------------------------------------------------------------
extern "C" void kernel_launch(void* const* d_in, const int* in_sizes, int n_in,
                              void* d_out, int out_size) {
    const float* X  = (const float*)d_in[0];
    const float* W0 = (const float*)d_in[1];
    const float* b0 = (const float*)d_in[2];
    const float* W1 = (const float*)d_in[3];
    const float* b1 = (const float*)d_in[4];
    const float* W2 = (const float*)d_in[5];
    const float* b2 = (const float*)d_in[6];
    float* out = (float*)d_out;

    const int smem_bytes = (11264 + P_ * XROW_ + 128) * (int)sizeof(float);  // ~110.5 KB
    cudaFuncSetAttribute(cmlp_kernel, cudaFuncAttributeMaxDynamicSharedMemorySize,
                         smem_bytes);

    prep_weights<<<256, 256>>>(W0, W1);

    dim3 grid((TOUT_ + TILE_ - 1) / TILE_, P_, B_);  // (8, 64, 16)
    cmlp_kernel<<<grid, NT_, smem_bytes>>>(X, b0, b1, W2, b2, out);
}

// round 4
// speedup vs baseline: 1.6163x; 1.6163x over previous
#include <cuda_runtime.h>
#include <cuda_bf16.h>
#include <cstdint>

#define T_     2048
#define P_     64
#define TOUT_  2044
#define NT_    256
#define TILE_  256
#define HALO_  260      // TILE + LAG - 1

// smem byte offsets
#define SM_X0    0            // X hi (260 rows x 128B) ; later H for net0
#define SM_X1    33280        // X lo ; later H for net1
#define SM_W0F   66560        // 2 nets x 40960B of W0 fragments
#define SM_W1F   148480       // 2 nets x 4096B of W1 fragments
#define SM_BIAS  156672       // 2 nets x 128 floats (b0|b1|W2|b2)
#define SM_RES   157696       // 256 x 2 floats
#define SM_TOTAL 159744

// pre-packed mma B-fragments (bf16 pairs, per-lane layout)
__device__ uint2 g_W0f[64 * 5 * 4 * 4 * 2 * 32];  // [n][l][cc][nt][part][lane]
__device__ uint2 g_W1f[64 * 4 * 4 * 32];          // [n][f][nt][lane]

__device__ __forceinline__ uint32_t pkbf(float a, float b) {
    __nv_bfloat162 t = __floats2bfloat162_rn(a, b);
    return *(uint32_t*)&t;
}
__device__ __forceinline__ float bflo(float v) {   // residual after bf16 round
    return v - __bfloat162float(__float2bfloat16_rn(v));
}

__device__ __forceinline__ void mma16816(float* d, const uint32_t* a, uint2 b) {
    asm volatile(
        "mma.sync.aligned.m16n8k16.row.col.f32.bf16.bf16.f32 "
        "{%0,%1,%2,%3}, {%4,%5,%6,%7}, {%8,%9}, {%0,%1,%2,%3};"
        : "+f"(d[0]), "+f"(d[1]), "+f"(d[2]), "+f"(d[3])
        : "r"(a[0]), "r"(a[1]), "r"(a[2]), "r"(a[3]), "r"(b.x), "r"(b.y));
}

// A-fragment load from swizzled [row][64c bf16] buffer (128B rows)
__device__ __forceinline__ void ldA(uint32_t* a, const char* buf,
                                    int rowBase, int kBase, int lane) {
    const int r = lane >> 2, c0 = (lane & 3) * 2;
    const int r0 = rowBase + r, r1 = r0 + 8;
    const int k0 = kBase + c0;
    a[0] = *(const uint32_t*)(buf + r0 * 128 + ((k0 * 2) ^ ((r0 & 7) << 4)));
    a[1] = *(const uint32_t*)(buf + r1 * 128 + ((k0 * 2) ^ ((r1 & 7) << 4)));
    a[2] = *(const uint32_t*)(buf + r0 * 128 + (((k0 + 8) * 2) ^ ((r0 & 7) << 4)));
    a[3] = *(const uint32_t*)(buf + r1 * 128 + (((k0 + 8) * 2) ^ ((r1 & 7) << 4)));
}

// ---------------- prep: pack weights into mma B-fragment layout ----------------
__global__ void prep(const float* __restrict__ W0, const float* __restrict__ W1) {
    const int id = blockIdx.x * blockDim.x + threadIdx.x;
    const int stride = gridDim.x * blockDim.x;

    // W0 fragments: [n][l][cc][nt][part][lane]
    for (int d = id; d < 64 * 5 * 4 * 4 * 2 * 32; d += stride) {
        int lane = d & 31;
        int rr = d >> 5;
        int part = rr & 1; rr >>= 1;
        int nt = rr & 3;   rr >>= 2;
        int cc = rr & 3;   rr >>= 2;
        int l = rr % 5, n = rr / 5;
        int k0 = (lane & 3) * 2;
        int h = nt * 8 + (lane >> 2);
        float v[4];
#pragma unroll
        for (int j = 0; j < 4; ++j) {
            int k = k0 + ((j >> 1) * 8) + (j & 1);
            v[j] = W0[((n * 32 + h) * 64 + (cc * 16 + k)) * 5 + l];
        }
        if (part) {
#pragma unroll
            for (int j = 0; j < 4; ++j) v[j] = bflo(v[j]);
        }
        g_W0f[d] = make_uint2(pkbf(v[0], v[1]), pkbf(v[2], v[3]));
    }

    // W1 fragments: f0,f1 = hi (i = k, 16+k), f2,f3 = lo
    for (int d = id; d < 64 * 4 * 4 * 32; d += stride) {
        int lane = d & 31;
        int rr = d >> 5;
        int nt = rr & 3; rr >>= 2;
        int f = rr & 3;
        int n = rr >> 2;
        int k0 = (lane & 3) * 2;
        int o = nt * 8 + (lane >> 2);
        int ib = (f & 1) * 16;
        float v[4];
#pragma unroll
        for (int j = 0; j < 4; ++j) {
            int k = k0 + ((j >> 1) * 8) + (j & 1);
            v[j] = W1[(n * 32 + o) * 32 + ib + k];
        }
        if (f >= 2) {
#pragma unroll
            for (int j = 0; j < 4; ++j) v[j] = bflo(v[j]);
        }
        g_W1f[d] = make_uint2(pkbf(v[0], v[1]), pkbf(v[2], v[3]));
    }
}

// ---------------- main ----------------
__global__ __launch_bounds__(NT_, 1)
void cmlp_mma(const float* __restrict__ X,
              const float* __restrict__ b0,
              const float* __restrict__ b1,
              const float* __restrict__ W2,
              const float* __restrict__ b2,
              float* __restrict__ out) {
    extern __shared__ char sm[];
    const int tid = threadIdx.x, warp = tid >> 5, lane = tid & 31;
    const int g = warp >> 2;        // net within pair
    const int wm = warp & 3;        // 64-row M slice
    const int nb = blockIdx.x * 2;  // first net
    const int p = blockIdx.y;
    const int bbt = p >> 3;
    const int t0 = (p & 7) * TILE_;

    // ---- weights + bias -> smem ----
    {
        const float4* s0 = (const float4*)(g_W0f + (size_t)nb * 5120);
        float4* d0 = (float4*)(sm + SM_W0F);
        for (int i = tid; i < 5120; i += NT_) d0[i] = s0[i];
        const float4* s1 = (const float4*)(g_W1f + (size_t)nb * 512);
        float4* d1 = (float4*)(sm + SM_W1F);
        for (int i = tid; i < 512; i += NT_) d1[i] = s1[i];
        float* bs = (float*)(sm + SM_BIAS);
        if (tid < 64) {
            int gg = tid >> 5, j = tid & 31, n = nb + gg;
            bs[gg * 128 + j]      = b0[n * 32 + j];
            bs[gg * 128 + 32 + j] = b1[n * 32 + j];
            bs[gg * 128 + 64 + j] = W2[n * 32 + j];
            if (j == 0) bs[gg * 128 + 96] = b2[n];
        }
    }

    // ---- stage X tile (bf16 hi/lo split, swizzled [row][c]) ----
    {
        const float* Xb = X + (size_t)bbt * T_ * P_;
        char* hiB = sm + SM_X0;
        char* loB = sm + SM_X1;
        for (int m = tid; m < HALO_ * 16; m += NT_) {
            int row = m >> 4, q = m & 15;
            int gr = t0 + row;
            float4 v = make_float4(0.f, 0.f, 0.f, 0.f);
            if (gr < T_) v = *(const float4*)(Xb + (size_t)gr * P_ + q * 4);
            uint2 hv = make_uint2(pkbf(v.x, v.y), pkbf(v.z, v.w));
            uint2 lv = make_uint2(pkbf(bflo(v.x), bflo(v.y)),
                                  pkbf(bflo(v.z), bflo(v.w)));
            int byte = row * 128 + ((q * 8) ^ ((row & 7) << 4));
            *(uint2*)(hiB + byte) = hv;
            *(uint2*)(loB + byte) = lv;
        }
    }
    __syncthreads();

    const float* bs = (const float*)(sm + SM_BIAS) + g * 128;
    const char* Xhi = sm + SM_X0;
    const char* Xlo = sm + SM_X1;
    const uint2* W0f = (const uint2*)(sm + SM_W0F) + g * 5120;
    const uint2* W1f = (const uint2*)(sm + SM_W1F) + g * 512;
    const int r = lane >> 2, c0 = (lane & 3) * 2;

    // ---- layer 0: M64 x N32, K=320, 3-product bf16 split ----
    float acc[4][4][4];
#pragma unroll
    for (int mt = 0; mt < 4; ++mt)
#pragma unroll
        for (int nt = 0; nt < 4; ++nt)
#pragma unroll
            for (int e = 0; e < 4; ++e)
                acc[mt][nt][e] = bs[nt * 8 + c0 + (e & 1)];

#pragma unroll 1
    for (int l = 0; l < 5; ++l) {
#pragma unroll 1
        for (int cc = 0; cc < 4; ++cc) {
            uint32_t ah[4][4], al[4][4];
#pragma unroll
            for (int mt = 0; mt < 4; ++mt) {
                ldA(ah[mt], Xhi, wm * 64 + mt * 16 + l, cc * 16, lane);
                ldA(al[mt], Xlo, wm * 64 + mt * 16 + l, cc * 16, lane);
            }
            uint2 wh[4], wl[4];
            const int fb = ((l * 4 + cc) * 4) * 2;
#pragma unroll
            for (int nt = 0; nt < 4; ++nt) {
                wh[nt] = W0f[(fb + nt * 2 + 0) * 32 + lane];
                wl[nt] = W0f[(fb + nt * 2 + 1) * 32 + lane];
            }
#pragma unroll
            for (int mt = 0; mt < 4; ++mt)
#pragma unroll
                for (int nt = 0; nt < 4; ++nt) {
                    mma16816(acc[mt][nt], ah[mt], wh[nt]);
                    mma16816(acc[mt][nt], ah[mt], wl[nt]);
                    mma16816(acc[mt][nt], al[mt], wh[nt]);
                }
        }
    }
    __syncthreads();   // everyone done reading X before H overlays it

    // ---- relu + split -> H (overlay X buffers; hi at c=i, lo at c=i+32) ----
    char* Hb = (char*)(sm + (g == 0 ? SM_X0 : SM_X1));
#pragma unroll
    for (int mt = 0; mt < 4; ++mt)
#pragma unroll
        for (int half = 0; half < 2; ++half) {
            int m = wm * 64 + mt * 16 + r + 8 * half;
#pragma unroll
            for (int nt = 0; nt < 4; ++nt) {
                float v0 = fmaxf(acc[mt][nt][half * 2 + 0], 0.f);
                float v1 = fmaxf(acc[mt][nt][half * 2 + 1], 0.f);
                int n = nt * 8 + c0;
                *(uint32_t*)(Hb + m * 128 + ((n * 2) ^ ((m & 7) << 4))) =
                    pkbf(v0, v1);
                *(uint32_t*)(Hb + m * 128 + (((n + 32) * 2) ^ ((m & 7) << 4))) =
                    pkbf(bflo(v0), bflo(v1));
            }
        }
    __syncwarp();   // warp reads only its own rows below

    // ---- layer 1: K=64 pass (hiH|loH vs hiW1) + K=32 pass (hiH vs loW1) ----
    float acc1[4][4][4];
#pragma unroll
    for (int mt = 0; mt < 4; ++mt)
#pragma unroll
        for (int nt = 0; nt < 4; ++nt)
#pragma unroll
            for (int e = 0; e < 4; ++e)
                acc1[mt][nt][e] = bs[32 + nt * 8 + c0 + (e & 1)];

#pragma unroll 1
    for (int kc = 0; kc < 4; ++kc) {
        uint32_t a[4][4];
#pragma unroll
        for (int mt = 0; mt < 4; ++mt)
            ldA(a[mt], Hb, wm * 64 + mt * 16, kc * 16, lane);
        const int f = kc & 1;
#pragma unroll
        for (int nt = 0; nt < 4; ++nt) {
            uint2 w = W1f[(f * 4 + nt) * 32 + lane];
#pragma unroll
            for (int mt = 0; mt < 4; ++mt) mma16816(acc1[mt][nt], a[mt], w);
        }
    }
#pragma unroll 1
    for (int kc = 0; kc < 2; ++kc) {
        uint32_t a[4][4];
#pragma unroll
        for (int mt = 0; mt < 4; ++mt)
            ldA(a[mt], Hb, wm * 64 + mt * 16, kc * 16, lane);
        const int f = 2 + kc;
#pragma unroll
        for (int nt = 0; nt < 4; ++nt) {
            uint2 w = W1f[(f * 4 + nt) * 32 + lane];
#pragma unroll
            for (int mt = 0; mt < 4; ++mt) mma16816(acc1[mt][nt], a[mt], w);
        }
    }

    // ---- layer 2: dot with W2, shfl-reduce over lane%4 group ----
    float* res = (float*)(sm + SM_RES);
#pragma unroll
    for (int mt = 0; mt < 4; ++mt)
#pragma unroll
        for (int half = 0; half < 2; ++half) {
            float s = 0.f;
#pragma unroll
            for (int nt = 0; nt < 4; ++nt)
#pragma unroll
                for (int e = 0; e < 2; ++e) {
                    int n = nt * 8 + c0 + e;
                    s = fmaf(fmaxf(acc1[mt][nt][half * 2 + e], 0.f),
                             bs[64 + n], s);
                }
            s += __shfl_xor_sync(0xFFFFFFFFu, s, 1);
            s += __shfl_xor_sync(0xFFFFFFFFu, s, 2);
            if ((lane & 3) == 0)
                res[(wm * 64 + mt * 16 + r + 8 * half) * 2 + g] = s + bs[96];
        }
    __syncthreads();

    // ---- store: float2 per timestep (both nets) ----
    {
        int t = t0 + tid;
        if (t < TOUT_)
            *(float2*)(out + ((size_t)bbt * TOUT_ + t) * P_ + nb) =
                *(const float2*)(res + tid * 2);
    }
}

// ---------------- launch ----------------
extern "C" void kernel_launch(void* const* d_in, const int* in_sizes, int n_in,
                              void* d_out, int out_size) {
    const float* X  = (const float*)d_in[0];
    const float* W0 = (const float*)d_in[1];
    const float* b0 = (const float*)d_in[2];
    const float* W1 = (const float*)d_in[3];
    const float* b1 = (const float*)d_in[4];
    const float* W2 = (const float*)d_in[5];
    const float* b2 = (const float*)d_in[6];
    float* out = (float*)d_out;

    cudaFuncSetAttribute(cmlp_mma, cudaFuncAttributeMaxDynamicSharedMemorySize,
                         SM_TOTAL);
    prep<<<256, 256>>>(W0, W1);
    dim3 grid(P_ / 2, 128);   // 32 net-pairs x (8 tiles x 16 batches)
    cmlp_mma<<<grid, NT_, SM_TOTAL>>>(X, b0, b1, W2, b2, out);
}

// round 5
// speedup vs baseline: 2.1764x; 1.3465x over previous
#include <cuda_runtime.h>
#include <cuda_bf16.h>
#include <cstdint>

#define T_     2048
#define P_     64
#define TOUT_  2044
#define NT_    256
#define TILE_  256
#define HALO_  260      // TILE + LAG - 1

// smem byte offsets (one net per block)
#define SM_X0    0            // X hi (260 rows x 128B) ; later H
#define SM_X1    33280        // X lo
#define SM_W0F   66560        // 40960B W0 fragments
#define SM_W1F   107520       // 4096B  W1 fragments
#define SM_BIAS  111616       // 128 floats (b0|b1|W2|b2)
#define SM_RES   112128       // 256 floats
#define SM_TOTAL 113152       // ~110.5 KB -> 2 blocks/SM

// pre-packed mma B-fragments (bf16 pairs, per-lane layout)
__device__ uint2 g_W0f[64 * 5 * 4 * 4 * 2 * 32];  // [n][l][cc][nt][part][lane]
__device__ uint2 g_W1f[64 * 4 * 4 * 32];          // [n][f][nt][lane]

__device__ __forceinline__ uint32_t pkbf(float a, float b) {
    __nv_bfloat162 t = __floats2bfloat162_rn(a, b);
    return *(uint32_t*)&t;
}
__device__ __forceinline__ float bflo(float v) {
    return v - __bfloat162float(__float2bfloat16_rn(v));
}
__device__ __forceinline__ uint32_t smem_u32(const void* p) {
    uint32_t a;
    asm("{ .reg .u64 t; cvta.to.shared.u64 t, %1; cvt.u32.u64 %0, t; }" : "=r"(a) : "l"(p));
    return a;
}

__device__ __forceinline__ void mma16816(float* d, const uint32_t* a, uint2 b) {
    asm volatile(
        "mma.sync.aligned.m16n8k16.row.col.f32.bf16.bf16.f32 "
        "{%0,%1,%2,%3}, {%4,%5,%6,%7}, {%8,%9}, {%0,%1,%2,%3};"
        : "+f"(d[0]), "+f"(d[1]), "+f"(d[2]), "+f"(d[3])
        : "r"(a[0]), "r"(a[1]), "r"(a[2]), "r"(a[3]), "r"(b.x), "r"(b.y));
}
__device__ __forceinline__ void ldsm4(uint32_t* a, uint32_t addr) {
    asm volatile("ldmatrix.sync.aligned.m8n8.x4.shared.b16 {%0,%1,%2,%3}, [%4];"
        : "=r"(a[0]), "=r"(a[1]), "=r"(a[2]), "=r"(a[3]) : "r"(addr));
}

// per-lane ldmatrix address into swizzled [row][64 bf16] tile (128B rows)
__device__ __forceinline__ uint32_t lmAddr(uint32_t buf, int rowBase, int kBase,
                                           int rl, int kl) {
    int row = rowBase + rl;
    int col = kBase + kl;
    return buf + row * 128 + ((col * 2) ^ ((row & 7) << 4));
}

// ---------------- prep: pack weights into mma B-fragment layout ----------------
__global__ void prep(const float* __restrict__ W0, const float* __restrict__ W1) {
    const int id = blockIdx.x * blockDim.x + threadIdx.x;
    const int stride = gridDim.x * blockDim.x;

    for (int d = id; d < 64 * 5 * 4 * 4 * 2 * 32; d += stride) {
        int lane = d & 31;
        int rr = d >> 5;
        int part = rr & 1; rr >>= 1;
        int nt = rr & 3;   rr >>= 2;
        int cc = rr & 3;   rr >>= 2;
        int l = rr % 5, n = rr / 5;
        int k0 = (lane & 3) * 2;
        int h = nt * 8 + (lane >> 2);
        float v[4];
#pragma unroll
        for (int j = 0; j < 4; ++j) {
            int k = k0 + ((j >> 1) * 8) + (j & 1);
            v[j] = W0[((n * 32 + h) * 64 + (cc * 16 + k)) * 5 + l];
        }
        if (part) {
#pragma unroll
            for (int j = 0; j < 4; ++j) v[j] = bflo(v[j]);
        }
        g_W0f[d] = make_uint2(pkbf(v[0], v[1]), pkbf(v[2], v[3]));
    }

    for (int d = id; d < 64 * 4 * 4 * 32; d += stride) {
        int lane = d & 31;
        int rr = d >> 5;
        int nt = rr & 3; rr >>= 2;
        int f = rr & 3;
        int n = rr >> 2;
        int k0 = (lane & 3) * 2;
        int o = nt * 8 + (lane >> 2);
        int ib = (f & 1) * 16;
        float v[4];
#pragma unroll
        for (int j = 0; j < 4; ++j) {
            int k = k0 + ((j >> 1) * 8) + (j & 1);
            v[j] = W1[(n * 32 + o) * 32 + ib + k];
        }
        if (f >= 2) {
#pragma unroll
            for (int j = 0; j < 4; ++j) v[j] = bflo(v[j]);
        }
        g_W1f[d] = make_uint2(pkbf(v[0], v[1]), pkbf(v[2], v[3]));
    }
}

// ---------------- main ----------------
__global__ __launch_bounds__(NT_, 2)
void cmlp_mma(const float* __restrict__ X,
              const float* __restrict__ b0,
              const float* __restrict__ b1,
              const float* __restrict__ W2,
              const float* __restrict__ b2,
              float* __restrict__ out) {
    extern __shared__ char sm[];
    const uint32_t sb = smem_u32(sm);
    const int tid = threadIdx.x, warp = tid >> 5, lane = tid & 31;
    const int n = blockIdx.x;       // net
    const int p = blockIdx.y;
    const int bbt = p >> 3;
    const int t0 = (p & 7) * TILE_;

    // ---- weights + bias -> smem ----
    {
        const float4* s0 = (const float4*)(g_W0f + (size_t)n * 5120);
        float4* d0 = (float4*)(sm + SM_W0F);
        for (int i = tid; i < 2560; i += NT_) d0[i] = s0[i];
        const float4* s1 = (const float4*)(g_W1f + (size_t)n * 512);
        float4* d1 = (float4*)(sm + SM_W1F);
        if (tid < 256) d1[tid] = s1[tid];
        float* bs = (float*)(sm + SM_BIAS);
        if (tid < 32) {
            bs[tid]      = b0[n * 32 + tid];
            bs[32 + tid] = b1[n * 32 + tid];
            bs[64 + tid] = W2[n * 32 + tid];
            if (tid == 0) bs[96] = b2[n];
        }
    }

    // ---- stage X tile (bf16 hi/lo split, swizzled [row][c]) ----
    {
        const float* Xb = X + (size_t)bbt * T_ * P_;
        char* hiB = sm + SM_X0;
        char* loB = sm + SM_X1;
        for (int m = tid; m < HALO_ * 16; m += NT_) {
            int row = m >> 4, q = m & 15;
            int gr = t0 + row;
            float4 v = make_float4(0.f, 0.f, 0.f, 0.f);
            if (gr < T_) v = *(const float4*)(Xb + (size_t)gr * P_ + q * 4);
            uint2 hv = make_uint2(pkbf(v.x, v.y), pkbf(v.z, v.w));
            uint2 lv = make_uint2(pkbf(bflo(v.x), bflo(v.y)),
                                  pkbf(bflo(v.z), bflo(v.w)));
            int byte = row * 128 + ((q * 8) ^ ((row & 7) << 4));
            *(uint2*)(hiB + byte) = hv;
            *(uint2*)(loB + byte) = lv;
        }
    }
    __syncthreads();

    const float* bs = (const float*)(sm + SM_BIAS);
    const uint32_t Xhi = sb + SM_X0;
    const uint32_t Xlo = sb + SM_X1;
    const uint2* W0f = (const uint2*)(sm + SM_W0F);
    const uint2* W1f = (const uint2*)(sm + SM_W1F);
    const int r = lane >> 2, c0 = (lane & 3) * 2;
    const int rl = lane & 15, kl = (lane >> 4) << 3;   // ldmatrix lane mapping

    // ---- layer 0: warp owns 32 rows (2 m-tiles), N32, K=320, 3-product split ----
    float acc[2][4][4];
#pragma unroll
    for (int mt = 0; mt < 2; ++mt)
#pragma unroll
        for (int nt = 0; nt < 4; ++nt)
#pragma unroll
            for (int e = 0; e < 4; ++e)
                acc[mt][nt][e] = bs[nt * 8 + c0 + (e & 1)];

#pragma unroll 1
    for (int l = 0; l < 5; ++l) {
#pragma unroll 1
        for (int cc = 0; cc < 4; ++cc) {
            uint32_t ah[2][4], al[2][4];
#pragma unroll
            for (int mt = 0; mt < 2; ++mt) {
                int rowBase = warp * 32 + mt * 16 + l;
                ldsm4(ah[mt], lmAddr(Xhi, rowBase, cc * 16, rl, kl));
                ldsm4(al[mt], lmAddr(Xlo, rowBase, cc * 16, rl, kl));
            }
            uint2 wh[4], wl[4];
            const int fb = ((l * 4 + cc) * 4) * 2;
#pragma unroll
            for (int nt = 0; nt < 4; ++nt) {
                wh[nt] = W0f[(fb + nt * 2 + 0) * 32 + lane];
                wl[nt] = W0f[(fb + nt * 2 + 1) * 32 + lane];
            }
#pragma unroll
            for (int mt = 0; mt < 2; ++mt)
#pragma unroll
                for (int nt = 0; nt < 4; ++nt) {
                    mma16816(acc[mt][nt], ah[mt], wh[nt]);
                    mma16816(acc[mt][nt], ah[mt], wl[nt]);
                    mma16816(acc[mt][nt], al[mt], wh[nt]);
                }
        }
    }
    __syncthreads();   // all layer0 X reads done before H overlays X0

    // ---- relu + split -> H (overlay X0; hi at col=i, lo at col=i+32) ----
    char* Hb = sm + SM_X0;
#pragma unroll
    for (int mt = 0; mt < 2; ++mt)
#pragma unroll
        for (int half = 0; half < 2; ++half) {
            int m = warp * 32 + mt * 16 + r + 8 * half;
#pragma unroll
            for (int nt = 0; nt < 4; ++nt) {
                float v0 = fmaxf(acc[mt][nt][half * 2 + 0], 0.f);
                float v1 = fmaxf(acc[mt][nt][half * 2 + 1], 0.f);
                int c = nt * 8 + c0;
                *(uint32_t*)(Hb + m * 128 + ((c * 2) ^ ((m & 7) << 4))) =
                    pkbf(v0, v1);
                *(uint32_t*)(Hb + m * 128 + (((c + 32) * 2) ^ ((m & 7) << 4))) =
                    pkbf(bflo(v0), bflo(v1));
            }
        }
    __syncwarp();   // warp reads only its own rows below

    // ---- layer 1: hiH*W1hi + loH*W1hi + hiH*W1lo ----
    float acc1[2][4][4];
#pragma unroll
    for (int mt = 0; mt < 2; ++mt)
#pragma unroll
        for (int nt = 0; nt < 4; ++nt)
#pragma unroll
            for (int e = 0; e < 4; ++e)
                acc1[mt][nt][e] = bs[32 + nt * 8 + c0 + (e & 1)];

#pragma unroll 1
    for (int kc = 0; kc < 4; ++kc) {            // H cols kc*16 (hi then lo)
        uint32_t a[2][4];
#pragma unroll
        for (int mt = 0; mt < 2; ++mt)
            ldsm4(a[mt], lmAddr(sb + SM_X0, warp * 32 + mt * 16, kc * 16, rl, kl));
        const int f = kc & 1;                   // W1 hi fragment (i-chunk)
#pragma unroll
        for (int nt = 0; nt < 4; ++nt) {
            uint2 w = W1f[(f * 4 + nt) * 32 + lane];
#pragma unroll
            for (int mt = 0; mt < 2; ++mt) mma16816(acc1[mt][nt], a[mt], w);
        }
    }
#pragma unroll 1
    for (int kc = 0; kc < 2; ++kc) {            // hiH x W1lo
        uint32_t a[2][4];
#pragma unroll
        for (int mt = 0; mt < 2; ++mt)
            ldsm4(a[mt], lmAddr(sb + SM_X0, warp * 32 + mt * 16, kc * 16, rl, kl));
        const int f = 2 + kc;
#pragma unroll
        for (int nt = 0; nt < 4; ++nt) {
            uint2 w = W1f[(f * 4 + nt) * 32 + lane];
#pragma unroll
            for (int mt = 0; mt < 2; ++mt) mma16816(acc1[mt][nt], a[mt], w);
        }
    }

    // ---- layer 2: dot with W2, shfl-reduce over lane%4 group ----
    float* res = (float*)(sm + SM_RES);
#pragma unroll
    for (int mt = 0; mt < 2; ++mt)
#pragma unroll
        for (int half = 0; half < 2; ++half) {
            float s = 0.f;
#pragma unroll
            for (int nt = 0; nt < 4; ++nt)
#pragma unroll
                for (int e = 0; e < 2; ++e) {
                    int c = nt * 8 + c0 + e;
                    s = fmaf(fmaxf(acc1[mt][nt][half * 2 + e], 0.f),
                             bs[64 + c], s);
                }
            s += __shfl_xor_sync(0xFFFFFFFFu, s, 1);
            s += __shfl_xor_sync(0xFFFFFFFFu, s, 2);
            if ((lane & 3) == 0)
                res[warp * 32 + mt * 16 + r + 8 * half] = s + bs[96];
        }
    __syncthreads();

    // ---- store ----
    {
        int t = t0 + tid;
        if (t < TOUT_)
            out[((size_t)bbt * TOUT_ + t) * P_ + n] = res[tid];
    }
}

// ---------------- launch ----------------
extern "C" void kernel_launch(void* const* d_in, const int* in_sizes, int n_in,
                              void* d_out, int out_size) {
    const float* X  = (const float*)d_in[0];
    const float* W0 = (const float*)d_in[1];
    const float* b0 = (const float*)d_in[2];
    const float* W1 = (const float*)d_in[3];
    const float* b1 = (const float*)d_in[4];
    const float* W2 = (const float*)d_in[5];
    const float* b2 = (const float*)d_in[6];
    float* out = (float*)d_out;

    cudaFuncSetAttribute(cmlp_mma, cudaFuncAttributeMaxDynamicSharedMemorySize,
                         SM_TOTAL);
    prep<<<256, 256>>>(W0, W1);
    dim3 grid(P_, 128);   // 64 nets x (8 tiles x 16 batches)
    cmlp_mma<<<grid, NT_, SM_TOTAL>>>(X, b0, b1, W2, b2, out);
}

// round 6
// speedup vs baseline: 2.3418x; 1.0760x over previous
#include <cuda_runtime.h>
#include <cuda_bf16.h>
#include <cstdint>

#define T_     2048
#define P_     64
#define TOUT_  2044
#define NT_    256
#define TILE_  256
#define HALO_  260      // TILE + LAG - 1

// smem byte offsets (one net per block)
#define SM_X0    0            // X hi (260 rows x 128B) ; later H
#define SM_X1    33280        // X lo
#define SM_W0F   66560        // 40960B W0 fragments
#define SM_W1F   107520       // 4096B  W1 fragments
#define SM_BIAS  111616       // 128 floats (b0|b1|W2|b2)
#define SM_RES   112128       // 256 floats
#define SM_TOTAL 113152       // ~110.5 KB -> 2 blocks/SM

// pre-packed mma B-fragments (bf16 pairs, per-lane layout)
__device__ uint2 g_W0f[64 * 5 * 4 * 4 * 2 * 32];  // [n][l][cc][nt][part][lane]
__device__ uint2 g_W1f[64 * 4 * 4 * 32];          // [n][f][nt][lane]

__device__ __forceinline__ uint32_t pkbf(float a, float b) {
    __nv_bfloat162 t = __floats2bfloat162_rn(a, b);
    return *(uint32_t*)&t;
}
__device__ __forceinline__ float bflo(float v) {
    return v - __bfloat162float(__float2bfloat16_rn(v));
}
__device__ __forceinline__ uint32_t smem_u32(const void* p) {
    uint32_t a;
    asm("{ .reg .u64 t; cvta.to.shared.u64 t, %1; cvt.u32.u64 %0, t; }" : "=r"(a) : "l"(p));
    return a;
}

__device__ __forceinline__ void mma16816(float* d, const uint32_t* a, uint2 b) {
    asm volatile(
        "mma.sync.aligned.m16n8k16.row.col.f32.bf16.bf16.f32 "
        "{%0,%1,%2,%3}, {%4,%5,%6,%7}, {%8,%9}, {%0,%1,%2,%3};"
        : "+f"(d[0]), "+f"(d[1]), "+f"(d[2]), "+f"(d[3])
        : "r"(a[0]), "r"(a[1]), "r"(a[2]), "r"(a[3]), "r"(b.x), "r"(b.y));
}
__device__ __forceinline__ void ldsm4(uint32_t* a, uint32_t addr) {
    asm volatile("ldmatrix.sync.aligned.m8n8.x4.shared.b16 {%0,%1,%2,%3}, [%4];"
        : "=r"(a[0]), "=r"(a[1]), "=r"(a[2]), "=r"(a[3]) : "r"(addr));
}

// per-lane ldmatrix address into swizzled [row][64 bf16] tile (128B rows)
__device__ __forceinline__ uint32_t lmAddr(uint32_t buf, int rowBase, int kBase,
                                           int rl, int kl) {
    int row = rowBase + rl;
    int col = kBase + kl;
    return buf + row * 128 + ((col * 2) ^ ((row & 7) << 4));
}

// ---------------- prep: pack weights into mma B-fragment layout ----------------
__global__ void prep(const float* __restrict__ W0, const float* __restrict__ W1) {
    const int id = blockIdx.x * blockDim.x + threadIdx.x;
    const int stride = gridDim.x * blockDim.x;

    for (int d = id; d < 64 * 5 * 4 * 4 * 2 * 32; d += stride) {
        int lane = d & 31;
        int rr = d >> 5;
        int part = rr & 1; rr >>= 1;
        int nt = rr & 3;   rr >>= 2;
        int cc = rr & 3;   rr >>= 2;
        int l = rr % 5, n = rr / 5;
        int k0 = (lane & 3) * 2;
        int h = nt * 8 + (lane >> 2);
        float v[4];
#pragma unroll
        for (int j = 0; j < 4; ++j) {
            int k = k0 + ((j >> 1) * 8) + (j & 1);
            v[j] = W0[((n * 32 + h) * 64 + (cc * 16 + k)) * 5 + l];
        }
        if (part) {
#pragma unroll
            for (int j = 0; j < 4; ++j) v[j] = bflo(v[j]);
        }
        g_W0f[d] = make_uint2(pkbf(v[0], v[1]), pkbf(v[2], v[3]));
    }

    for (int d = id; d < 64 * 4 * 4 * 32; d += stride) {
        int lane = d & 31;
        int rr = d >> 5;
        int nt = rr & 3; rr >>= 2;
        int f = rr & 3;
        int n = rr >> 2;
        int k0 = (lane & 3) * 2;
        int o = nt * 8 + (lane >> 2);
        int ib = (f & 1) * 16;
        float v[4];
#pragma unroll
        for (int j = 0; j < 4; ++j) {
            int k = k0 + ((j >> 1) * 8) + (j & 1);
            v[j] = W1[(n * 32 + o) * 32 + ib + k];
        }
        if (f >= 2) {
#pragma unroll
            for (int j = 0; j < 4; ++j) v[j] = bflo(v[j]);
        }
        g_W1f[d] = make_uint2(pkbf(v[0], v[1]), pkbf(v[2], v[3]));
    }
}

// ---- pipelined layer0 helpers ----
struct Frag {
    uint32_t ah[2][4], al[2][4];
    uint2 wh[4], wl[4];
};

__device__ __forceinline__ void ld_step(Frag& f, int l, int cc, int warp,
                                        int lane, int rl, int kl,
                                        uint32_t Xhi, uint32_t Xlo,
                                        const uint2* __restrict__ W0f) {
#pragma unroll
    for (int mt = 0; mt < 2; ++mt) {
        int rowBase = warp * 32 + mt * 16 + l;
        ldsm4(f.ah[mt], lmAddr(Xhi, rowBase, cc * 16, rl, kl));
        ldsm4(f.al[mt], lmAddr(Xlo, rowBase, cc * 16, rl, kl));
    }
    const int fb = ((l * 4 + cc) * 4) * 2;
#pragma unroll
    for (int nt = 0; nt < 4; ++nt) {
        f.wh[nt] = W0f[(fb + nt * 2 + 0) * 32 + lane];
        f.wl[nt] = W0f[(fb + nt * 2 + 1) * 32 + lane];
    }
}

__device__ __forceinline__ void mma_step(float acc[2][4][4], const Frag& f) {
#pragma unroll
    for (int mt = 0; mt < 2; ++mt)
#pragma unroll
        for (int nt = 0; nt < 4; ++nt) {
            mma16816(acc[mt][nt], f.ah[mt], f.wh[nt]);
            mma16816(acc[mt][nt], f.ah[mt], f.wl[nt]);
            mma16816(acc[mt][nt], f.al[mt], f.wh[nt]);
        }
}

// ---------------- main ----------------
__global__ __launch_bounds__(NT_, 2)
void cmlp_mma(const float* __restrict__ X,
              const float* __restrict__ b0,
              const float* __restrict__ b1,
              const float* __restrict__ W2,
              const float* __restrict__ b2,
              float* __restrict__ out) {
    extern __shared__ char sm[];
    const uint32_t sb = smem_u32(sm);
    const int tid = threadIdx.x, warp = tid >> 5, lane = tid & 31;
    const int n = blockIdx.x;       // net
    const int p = blockIdx.y;
    const int bbt = p >> 3;
    const int t0 = (p & 7) * TILE_;

    // ---- weights + bias -> smem ----
    {
        const float4* s0 = (const float4*)(g_W0f + (size_t)n * 5120);
        float4* d0 = (float4*)(sm + SM_W0F);
        for (int i = tid; i < 2560; i += NT_) d0[i] = s0[i];
        const float4* s1 = (const float4*)(g_W1f + (size_t)n * 512);
        float4* d1 = (float4*)(sm + SM_W1F);
        if (tid < 256) d1[tid] = s1[tid];
        float* bs = (float*)(sm + SM_BIAS);
        if (tid < 32) {
            bs[tid]      = b0[n * 32 + tid];
            bs[32 + tid] = b1[n * 32 + tid];
            bs[64 + tid] = W2[n * 32 + tid];
            if (tid == 0) bs[96] = b2[n];
        }
    }

    // ---- stage X tile (bf16 hi/lo split, swizzled [row][c]) ----
    {
        const float* Xb = X + (size_t)bbt * T_ * P_;
        char* hiB = sm + SM_X0;
        char* loB = sm + SM_X1;
        for (int m = tid; m < HALO_ * 16; m += NT_) {
            int row = m >> 4, q = m & 15;
            int gr = t0 + row;
            float4 v = make_float4(0.f, 0.f, 0.f, 0.f);
            if (gr < T_) v = *(const float4*)(Xb + (size_t)gr * P_ + q * 4);
            uint2 hv = make_uint2(pkbf(v.x, v.y), pkbf(v.z, v.w));
            uint2 lv = make_uint2(pkbf(bflo(v.x), bflo(v.y)),
                                  pkbf(bflo(v.z), bflo(v.w)));
            int byte = row * 128 + ((q * 8) ^ ((row & 7) << 4));
            *(uint2*)(hiB + byte) = hv;
            *(uint2*)(loB + byte) = lv;
        }
    }
    __syncthreads();

    const float* bs = (const float*)(sm + SM_BIAS);
    const uint32_t Xhi = sb + SM_X0;
    const uint32_t Xlo = sb + SM_X1;
    const uint2* W0f = (const uint2*)(sm + SM_W0F);
    const uint2* W1f = (const uint2*)(sm + SM_W1F);
    const int r = lane >> 2, c0 = (lane & 3) * 2;
    const int rl = lane & 15, kl = (lane >> 4) << 3;   // ldmatrix lane mapping

    // ---- layer 0: warp owns 32 rows, N32, K=320, 3-product split, pipelined ----
    float acc[2][4][4];
#pragma unroll
    for (int mt = 0; mt < 2; ++mt)
#pragma unroll
        for (int nt = 0; nt < 4; ++nt)
#pragma unroll
            for (int e = 0; e < 4; ++e)
                acc[mt][nt][e] = bs[nt * 8 + c0 + (e & 1)];

    {
        Frag fA, fB;
        ld_step(fA, 0, 0, warp, lane, rl, kl, Xhi, Xlo, W0f);
#pragma unroll
        for (int s = 0; s < 20; s += 2) {
            const int s1 = s + 1, s2 = s + 2;
            ld_step(fB, s1 >> 2, s1 & 3, warp, lane, rl, kl, Xhi, Xlo, W0f);
            mma_step(acc, fA);
            if (s2 < 20)
                ld_step(fA, s2 >> 2, s2 & 3, warp, lane, rl, kl, Xhi, Xlo, W0f);
            mma_step(acc, fB);
        }
    }
    __syncthreads();   // all layer0 X reads done before H overlays X0

    // ---- relu + split -> H (overlay X0; hi at col=i, lo at col=i+32) ----
    char* Hb = sm + SM_X0;
#pragma unroll
    for (int mt = 0; mt < 2; ++mt)
#pragma unroll
        for (int half = 0; half < 2; ++half) {
            int m = warp * 32 + mt * 16 + r + 8 * half;
#pragma unroll
            for (int nt = 0; nt < 4; ++nt) {
                float v0 = fmaxf(acc[mt][nt][half * 2 + 0], 0.f);
                float v1 = fmaxf(acc[mt][nt][half * 2 + 1], 0.f);
                int c = nt * 8 + c0;
                *(uint32_t*)(Hb + m * 128 + ((c * 2) ^ ((m & 7) << 4))) =
                    pkbf(v0, v1);
                *(uint32_t*)(Hb + m * 128 + (((c + 32) * 2) ^ ((m & 7) << 4))) =
                    pkbf(bflo(v0), bflo(v1));
            }
        }
    __syncwarp();   // warp reads only its own rows below

    // ---- layer 1: hiH*W1hi + loH*W1hi + hiH*W1lo (6 pipelined steps) ----
    float acc1[2][4][4];
#pragma unroll
    for (int mt = 0; mt < 2; ++mt)
#pragma unroll
        for (int nt = 0; nt < 4; ++nt)
#pragma unroll
            for (int e = 0; e < 4; ++e)
                acc1[mt][nt][e] = bs[32 + nt * 8 + c0 + (e & 1)];

#pragma unroll
    for (int s = 0; s < 6; ++s) {
        // s 0..3: A = H cols s*16 (hi,lo interleaved halves), W1 hi frag (s&1)
        // s 4..5: A = hiH cols (s-4)*16, W1 lo frag
        const int kc = (s < 4) ? s : (s - 4);
        const int f  = (s < 4) ? (s & 1) : (s - 2);
        uint32_t a[2][4];
#pragma unroll
        for (int mt = 0; mt < 2; ++mt)
            ldsm4(a[mt], lmAddr(sb + SM_X0, warp * 32 + mt * 16, kc * 16, rl, kl));
#pragma unroll
        for (int nt = 0; nt < 4; ++nt) {
            uint2 w = W1f[(f * 4 + nt) * 32 + lane];
#pragma unroll
            for (int mt = 0; mt < 2; ++mt) mma16816(acc1[mt][nt], a[mt], w);
        }
    }

    // ---- layer 2: dot with W2, shfl-reduce over lane%4 group ----
    float* res = (float*)(sm + SM_RES);
#pragma unroll
    for (int mt = 0; mt < 2; ++mt)
#pragma unroll
        for (int half = 0; half < 2; ++half) {
            float s = 0.f;
#pragma unroll
            for (int nt = 0; nt < 4; ++nt)
#pragma unroll
                for (int e = 0; e < 2; ++e) {
                    int c = nt * 8 + c0 + e;
                    s = fmaf(fmaxf(acc1[mt][nt][half * 2 + e], 0.f),
                             bs[64 + c], s);
                }
            s += __shfl_xor_sync(0xFFFFFFFFu, s, 1);
            s += __shfl_xor_sync(0xFFFFFFFFu, s, 2);
            if ((lane & 3) == 0)
                res[warp * 32 + mt * 16 + r + 8 * half] = s + bs[96];
        }
    __syncthreads();

    // ---- store ----
    {
        int t = t0 + tid;
        if (t < TOUT_)
            out[((size_t)bbt * TOUT_ + t) * P_ + n] = res[tid];
    }
}

// ---------------- launch ----------------
extern "C" void kernel_launch(void* const* d_in, const int* in_sizes, int n_in,
                              void* d_out, int out_size) {
    const float* X  = (const float*)d_in[0];
    const float* W0 = (const float*)d_in[1];
    const float* b0 = (const float*)d_in[2];
    const float* W1 = (const float*)d_in[3];
    const float* b1 = (const float*)d_in[4];
    const float* W2 = (const float*)d_in[5];
    const float* b2 = (const float*)d_in[6];
    float* out = (float*)d_out;

    cudaFuncSetAttribute(cmlp_mma, cudaFuncAttributeMaxDynamicSharedMemorySize,
                         SM_TOTAL);
    prep<<<256, 256>>>(W0, W1);
    dim3 grid(P_, 128);   // 64 nets x (8 tiles x 16 batches)
    cmlp_mma<<<grid, NT_, SM_TOTAL>>>(X, b0, b1, W2, b2, out);
}

// round 7
// speedup vs baseline: 2.8018x; 1.1964x over previous
#include <cuda_runtime.h>
#include <cuda_bf16.h>
#include <cstdint>

#define T_     2048
#define TPAD_  2052
#define P_     64
#define TOUT_  2044
#define NT_    256
#define TILE_  256
#define HALO_  260      // TILE + LAG - 1

// smem byte offsets (one net per block, 3 blocks/SM)
#define SM_X0    0            // X hi (260 rows x 128B) ; later H
#define SM_X1    33280        // X lo
#define SM_W1F   66560        // 4096B W1 fragments
#define SM_BIAS  70656        // 128 floats (b0|b1|W2|b2)
#define SM_RES   71168        // 256 floats
#define SM_TOTAL 72192        // 70.5 KB -> 3 blocks/SM

// pre-packed weights / pre-converted X
__device__ uint2 g_W0f[64 * 5 * 4 * 4 * 2 * 32];   // [n][l][cc][nt][part][lane]
__device__ uint2 g_W1f[64 * 4 * 4 * 32];           // [n][f][nt][lane]
__device__ char  g_Xp[16 * 2 * TPAD_ * 128];       // [batch][hi/lo][row][128B swizzled]

__device__ __forceinline__ uint32_t pkbf(float a, float b) {
    __nv_bfloat162 t = __floats2bfloat162_rn(a, b);
    return *(uint32_t*)&t;
}
__device__ __forceinline__ float bflo(float v) {
    return v - __bfloat162float(__float2bfloat16_rn(v));
}
__device__ __forceinline__ uint32_t smem_u32(const void* p) {
    uint32_t a;
    asm("{ .reg .u64 t; cvta.to.shared.u64 t, %1; cvt.u32.u64 %0, t; }" : "=r"(a) : "l"(p));
    return a;
}

__device__ __forceinline__ void mma16816(float* d, const uint32_t* a, uint2 b) {
    asm volatile(
        "mma.sync.aligned.m16n8k16.row.col.f32.bf16.bf16.f32 "
        "{%0,%1,%2,%3}, {%4,%5,%6,%7}, {%8,%9}, {%0,%1,%2,%3};"
        : "+f"(d[0]), "+f"(d[1]), "+f"(d[2]), "+f"(d[3])
        : "r"(a[0]), "r"(a[1]), "r"(a[2]), "r"(a[3]), "r"(b.x), "r"(b.y));
}
__device__ __forceinline__ void ldsm4(uint32_t* a, uint32_t addr) {
    asm volatile("ldmatrix.sync.aligned.m8n8.x4.shared.b16 {%0,%1,%2,%3}, [%4];"
        : "=r"(a[0]), "=r"(a[1]), "=r"(a[2]), "=r"(a[3]) : "r"(addr));
}
__device__ __forceinline__ void cpa16(uint32_t dst, const void* src) {
    asm volatile("cp.async.cg.shared.global [%0], [%1], 16;" :: "r"(dst), "l"(src));
}
__device__ __forceinline__ void cpa_wait() {
    asm volatile("cp.async.commit_group;");
    asm volatile("cp.async.wait_group 0;" ::: "memory");
}

// per-lane ldmatrix address into swizzled [row][64 bf16] tile (128B rows)
__device__ __forceinline__ uint32_t lmAddr(uint32_t buf, int rowBase, int kBase,
                                           int rl, int kl) {
    int row = rowBase + rl;
    int col = kBase + kl;
    return buf + row * 128 + ((col * 2) ^ ((row & 7) << 4));
}

// ---------------- prep: pack weights + pre-convert X ----------------
__global__ void prep(const float* __restrict__ X,
                     const float* __restrict__ W0,
                     const float* __restrict__ W1) {
    const int id = blockIdx.x * blockDim.x + threadIdx.x;
    const int stride = gridDim.x * blockDim.x;

    // X -> bf16 hi/lo, swizzled 128B rows, zero-padded rows 2048..2051
    for (int d = id; d < 16 * TPAD_ * 16; d += stride) {
        int q = d & 15;
        int rr = d >> 4;
        int t = rr % TPAD_, bbt = rr / TPAD_;
        float4 v = make_float4(0.f, 0.f, 0.f, 0.f);
        if (t < T_) v = *(const float4*)(X + ((size_t)bbt * T_ + t) * P_ + q * 4);
        uint2 hv = make_uint2(pkbf(v.x, v.y), pkbf(v.z, v.w));
        uint2 lv = make_uint2(pkbf(bflo(v.x), bflo(v.y)),
                              pkbf(bflo(v.z), bflo(v.w)));
        int off = (q * 8) ^ ((t & 7) << 4);
        *(uint2*)(g_Xp + ((size_t)(bbt * 2 + 0) * TPAD_ + t) * 128 + off) = hv;
        *(uint2*)(g_Xp + ((size_t)(bbt * 2 + 1) * TPAD_ + t) * 128 + off) = lv;
    }

    for (int d = id; d < 64 * 5 * 4 * 4 * 2 * 32; d += stride) {
        int lane = d & 31;
        int rr = d >> 5;
        int part = rr & 1; rr >>= 1;
        int nt = rr & 3;   rr >>= 2;
        int cc = rr & 3;   rr >>= 2;
        int l = rr % 5, n = rr / 5;
        int k0 = (lane & 3) * 2;
        int h = nt * 8 + (lane >> 2);
        float v[4];
#pragma unroll
        for (int j = 0; j < 4; ++j) {
            int k = k0 + ((j >> 1) * 8) + (j & 1);
            v[j] = W0[((n * 32 + h) * 64 + (cc * 16 + k)) * 5 + l];
        }
        if (part) {
#pragma unroll
            for (int j = 0; j < 4; ++j) v[j] = bflo(v[j]);
        }
        g_W0f[d] = make_uint2(pkbf(v[0], v[1]), pkbf(v[2], v[3]));
    }

    for (int d = id; d < 64 * 4 * 4 * 32; d += stride) {
        int lane = d & 31;
        int rr = d >> 5;
        int nt = rr & 3; rr >>= 2;
        int f = rr & 3;
        int n = rr >> 2;
        int k0 = (lane & 3) * 2;
        int o = nt * 8 + (lane >> 2);
        int ib = (f & 1) * 16;
        float v[4];
#pragma unroll
        for (int j = 0; j < 4; ++j) {
            int k = k0 + ((j >> 1) * 8) + (j & 1);
            v[j] = W1[(n * 32 + o) * 32 + ib + k];
        }
        if (f >= 2) {
#pragma unroll
            for (int j = 0; j < 4; ++j) v[j] = bflo(v[j]);
        }
        g_W1f[d] = make_uint2(pkbf(v[0], v[1]), pkbf(v[2], v[3]));
    }
}

// ---------------- main ----------------
__global__ __launch_bounds__(NT_, 3)
void cmlp_mma(const float* __restrict__ b0,
              const float* __restrict__ b1,
              const float* __restrict__ W2,
              const float* __restrict__ b2,
              float* __restrict__ out) {
    extern __shared__ char sm[];
    const uint32_t sb = smem_u32(sm);
    const int tid = threadIdx.x, warp = tid >> 5, lane = tid & 31;
    const int n = blockIdx.x;       // net
    const int p = blockIdx.y;
    const int bbt = p >> 3;
    const int t0 = (p & 7) * TILE_;

    // ---- stage X tile (pure cp.async copies, pre-converted/pre-swizzled) ----
    {
        const char* gh = g_Xp + ((size_t)(bbt * 2 + 0) * TPAD_ + t0) * 128;
        const char* gl = g_Xp + ((size_t)(bbt * 2 + 1) * TPAD_ + t0) * 128;
        for (int m = tid; m < HALO_ * 8; m += NT_) {
            cpa16(sb + SM_X0 + m * 16, gh + m * 16);
            cpa16(sb + SM_X1 + m * 16, gl + m * 16);
        }
        // W1 fragments (4 KB) + bias
        const char* s1 = (const char*)(g_W1f + (size_t)n * 512);
        if (tid < 256) cpa16(sb + SM_W1F + tid * 16, s1 + tid * 16);
        float* bs = (float*)(sm + SM_BIAS);
        if (tid < 32) {
            bs[tid]      = b0[n * 32 + tid];
            bs[32 + tid] = b1[n * 32 + tid];
            bs[64 + tid] = W2[n * 32 + tid];
            if (tid == 0) bs[96] = b2[n];
        }
        cpa_wait();
    }
    __syncthreads();

    const float* bs = (const float*)(sm + SM_BIAS);
    const uint32_t Xhi = sb + SM_X0;
    const uint32_t Xlo = sb + SM_X1;
    const uint2* __restrict__ W0g = g_W0f + (size_t)n * 5120;
    const uint2* W1f = (const uint2*)(sm + SM_W1F);
    const int r = lane >> 2, c0 = (lane & 3) * 2;
    const int rl = lane & 15, kl = (lane >> 4) << 3;   // ldmatrix lane mapping

    // ---- layer 0: warp owns 32 rows, N32, K=320, 3-product split ----
    float acc[2][4][4];
#pragma unroll
    for (int mt = 0; mt < 2; ++mt)
#pragma unroll
        for (int nt = 0; nt < 4; ++nt)
#pragma unroll
            for (int e = 0; e < 4; ++e)
                acc[mt][nt][e] = bs[nt * 8 + c0 + (e & 1)];

#pragma unroll 1
    for (int s = 0; s < 20; ++s) {
        const int l = s >> 2, cc = s & 3;
        // W fragments from gmem (L2-resident); issue first so latency overlaps ldsm
        uint2 wh[4], wl[4];
#pragma unroll
        for (int nt = 0; nt < 4; ++nt) {
            wh[nt] = __ldg(&W0g[(s * 8 + nt * 2 + 0) * 32 + lane]);
            wl[nt] = __ldg(&W0g[(s * 8 + nt * 2 + 1) * 32 + lane]);
        }
        uint32_t ah[2][4], al[2][4];
#pragma unroll
        for (int mt = 0; mt < 2; ++mt) {
            int rowBase = warp * 32 + mt * 16 + l;
            ldsm4(ah[mt], lmAddr(Xhi, rowBase, cc * 16, rl, kl));
            ldsm4(al[mt], lmAddr(Xlo, rowBase, cc * 16, rl, kl));
        }
#pragma unroll
        for (int mt = 0; mt < 2; ++mt)
#pragma unroll
            for (int nt = 0; nt < 4; ++nt) {
                mma16816(acc[mt][nt], ah[mt], wh[nt]);
                mma16816(acc[mt][nt], ah[mt], wl[nt]);
                mma16816(acc[mt][nt], al[mt], wh[nt]);
            }
    }
    __syncthreads();   // all layer0 X reads done before H overlays X0

    // ---- relu + split -> H (overlay X0; hi at col=i, lo at col=i+32) ----
    char* Hb = sm + SM_X0;
#pragma unroll
    for (int mt = 0; mt < 2; ++mt)
#pragma unroll
        for (int half = 0; half < 2; ++half) {
            int m = warp * 32 + mt * 16 + r + 8 * half;
#pragma unroll
            for (int nt = 0; nt < 4; ++nt) {
                float v0 = fmaxf(acc[mt][nt][half * 2 + 0], 0.f);
                float v1 = fmaxf(acc[mt][nt][half * 2 + 1], 0.f);
                int c = nt * 8 + c0;
                *(uint32_t*)(Hb + m * 128 + ((c * 2) ^ ((m & 7) << 4))) =
                    pkbf(v0, v1);
                *(uint32_t*)(Hb + m * 128 + (((c + 32) * 2) ^ ((m & 7) << 4))) =
                    pkbf(bflo(v0), bflo(v1));
            }
        }
    __syncwarp();   // warp reads only its own rows below

    // ---- layer 1: hiH*W1hi + loH*W1hi + hiH*W1lo ----
    float acc1[2][4][4];
#pragma unroll
    for (int mt = 0; mt < 2; ++mt)
#pragma unroll
        for (int nt = 0; nt < 4; ++nt)
#pragma unroll
            for (int e = 0; e < 4; ++e)
                acc1[mt][nt][e] = bs[32 + nt * 8 + c0 + (e & 1)];

#pragma unroll
    for (int s = 0; s < 6; ++s) {
        const int kc = (s < 4) ? s : (s - 4);
        const int f  = (s < 4) ? (s & 1) : (s - 2);
        uint32_t a[2][4];
#pragma unroll
        for (int mt = 0; mt < 2; ++mt)
            ldsm4(a[mt], lmAddr(sb + SM_X0, warp * 32 + mt * 16, kc * 16, rl, kl));
#pragma unroll
        for (int nt = 0; nt < 4; ++nt) {
            uint2 w = W1f[(f * 4 + nt) * 32 + lane];
#pragma unroll
            for (int mt = 0; mt < 2; ++mt) mma16816(acc1[mt][nt], a[mt], w);
        }
    }

    // ---- layer 2: dot with W2, shfl-reduce over lane%4 group ----
    float* res = (float*)(sm + SM_RES);
#pragma unroll
    for (int mt = 0; mt < 2; ++mt)
#pragma unroll
        for (int half = 0; half < 2; ++half) {
            float s = 0.f;
#pragma unroll
            for (int nt = 0; nt < 4; ++nt)
#pragma unroll
                for (int e = 0; e < 2; ++e) {
                    int c = nt * 8 + c0 + e;
                    s = fmaf(fmaxf(acc1[mt][nt][half * 2 + e], 0.f),
                             bs[64 + c], s);
                }
            s += __shfl_xor_sync(0xFFFFFFFFu, s, 1);
            s += __shfl_xor_sync(0xFFFFFFFFu, s, 2);
            if ((lane & 3) == 0)
                res[warp * 32 + mt * 16 + r + 8 * half] = s + bs[96];
        }
    __syncthreads();

    // ---- store ----
    {
        int t = t0 + tid;
        if (t < TOUT_)
            out[((size_t)bbt * TOUT_ + t) * P_ + n] = res[tid];
    }
}

// ---------------- launch ----------------
extern "C" void kernel_launch(void* const* d_in, const int* in_sizes, int n_in,
                              void* d_out, int out_size) {
    const float* X  = (const float*)d_in[0];
    const float* W0 = (const float*)d_in[1];
    const float* b0 = (const float*)d_in[2];
    const float* W1 = (const float*)d_in[3];
    const float* b1 = (const float*)d_in[4];
    const float* W2 = (const float*)d_in[5];
    const float* b2 = (const float*)d_in[6];
    float* out = (float*)d_out;

    cudaFuncSetAttribute(cmlp_mma, cudaFuncAttributeMaxDynamicSharedMemorySize,
                         SM_TOTAL);
    prep<<<1024, 256>>>(X, W0, W1);
    dim3 grid(P_, 128);   // 64 nets x (8 tiles x 16 batches)
    cmlp_mma<<<grid, NT_, SM_TOTAL>>>(b0, b1, W2, b2, out);
}